// round 2
// baseline (speedup 1.0000x reference)
#include <cuda_runtime.h>

#define BATCH 4
#define SEQ   4096
#define DIM   64
#define BM    32            // query rows per task
#define BN    64            // keys per tile
#define NTASKS (BATCH * (SEQ / BM))   // 512
#define GRID  444           // ~3 persistent CTAs per SM
#define NEGV  10000.0f

__device__ int g_task_counter;

__global__ void reset_counter() { g_task_counter = 0; }

__global__ __launch_bounds__(256)
void sdpa_kernel(const float* __restrict__ Q, const float* __restrict__ K,
                 const float* __restrict__ V, const int* __restrict__ mask,
                 float* __restrict__ O) {
    __shared__ float Ks[BN][DIM];
    __shared__ float Vs[BN][DIM];
    __shared__ float pen[BN];
    __shared__ int cur_task;

    const int tid = threadIdx.x;
    const int r   = tid >> 3;          // row in q-block (0..31)
    const int sub = tid & 7;           // 8-dim slice of D
    const int d0  = sub * 8;

    for (;;) {
        if (tid == 0) cur_task = atomicAdd(&g_task_counter, 1);
        __syncthreads();
        const int t = cur_task;
        __syncthreads();                       // cur_task consumed before next overwrite
        if (t >= NTASKS) return;

        // descending work order: longest q-blocks first
        const int i  = (SEQ / BM - 1) - (t >> 2);   // q-block index 127..0
        const int b  = t & 3;
        const int qm = i * BM;
        const int q_idx = qm + r;
        const int* mb = mask + b * SEQ;

        // any mask==1 in the shared causal prefix [0..qm]?
        // If yes: beyond-diagonal scores are >=10000 below running max -> exp
        // underflows to exactly 0, skipping those tiles is bit-equivalent.
        int local_any = 0;
        for (int j = tid; j <= qm; j += 256) local_any |= mb[j];
        const int any_one = __syncthreads_or(local_any);
        const int n_tiles = any_one ? ((qm + BM + BN - 1) / BN) : (SEQ / BN);

        // q slice (8 dims) in registers
        const float4* qp = reinterpret_cast<const float4*>(
            Q + ((size_t)b * SEQ + q_idx) * DIM + d0);
        const float4 qa = qp[0], qb = qp[1];

        float4 oa = make_float4(0.f, 0.f, 0.f, 0.f);
        float4 ob = make_float4(0.f, 0.f, 0.f, 0.f);
        float m_run = -1e30f, l_run = 0.0f;

        for (int tt = 0; tt < n_tiles; tt++) {
            const int kv0 = tt * BN;
            {   // cooperative tile load, coalesced float4
                const float4* kp = reinterpret_cast<const float4*>(K + ((size_t)b * SEQ + kv0) * DIM);
                const float4* vp = reinterpret_cast<const float4*>(V + ((size_t)b * SEQ + kv0) * DIM);
                float4* ks4 = reinterpret_cast<float4*>(&Ks[0][0]);
                float4* vs4 = reinterpret_cast<float4*>(&Vs[0][0]);
                #pragma unroll
                for (int k = 0; k < 4; k++) {
                    ks4[tid + k * 256] = kp[tid + k * 256];
                    vs4[tid + k * 256] = vp[tid + k * 256];
                }
                if (tid < BN) pen[tid] = mb[kv0 + tid] ? 0.0f : -NEGV;
            }
            __syncthreads();

            const int jmax = q_idx - kv0;   // causal penalty when j > jmax

            #pragma unroll 1
            for (int jc = 0; jc < BN; jc += 8) {
                // --- 8 independent scores (dots + shfl trees pipeline) ---
                float s[8];
                #pragma unroll
                for (int jj = 0; jj < 8; jj++) {
                    const int j = jc + jj;
                    const float4* kr = reinterpret_cast<const float4*>(&Ks[j][d0]);
                    const float4 ka = kr[0], kb = kr[1];
                    float acc = qa.x * ka.x + qa.y * ka.y + qa.z * ka.z + qa.w * ka.w
                              + qb.x * kb.x + qb.y * kb.y + qb.z * kb.z + qb.w * kb.w;
                    acc += __shfl_xor_sync(0xffffffffu, acc, 1);
                    acc += __shfl_xor_sync(0xffffffffu, acc, 2);
                    acc += __shfl_xor_sync(0xffffffffu, acc, 4);
                    float sc = acc * 0.125f + pen[j];
                    if (j > jmax) sc -= NEGV;
                    s[jj] = sc;
                }
                float cmax = s[0];
                #pragma unroll
                for (int jj = 1; jj < 8; jj++) cmax = fmaxf(cmax, s[jj]);

                if (cmax > m_run) {         // rare rescale (once per few chunks)
                    const float alpha = __expf(m_run - cmax);
                    l_run *= alpha;
                    oa.x *= alpha; oa.y *= alpha; oa.z *= alpha; oa.w *= alpha;
                    ob.x *= alpha; ob.y *= alpha; ob.z *= alpha; ob.w *= alpha;
                    m_run = cmax;
                }
                #pragma unroll
                for (int jj = 0; jj < 8; jj++) {
                    const int j = jc + jj;
                    const float p = __expf(s[jj] - m_run);
                    l_run += p;
                    const float4* vr = reinterpret_cast<const float4*>(&Vs[j][d0]);
                    const float4 va = vr[0], vb = vr[1];
                    oa.x += p * va.x; oa.y += p * va.y; oa.z += p * va.z; oa.w += p * va.w;
                    ob.x += p * vb.x; ob.y += p * vb.y; ob.z += p * vb.z; ob.w += p * vb.w;
                }
            }
            __syncthreads();
        }

        const float inv = 1.0f / l_run;
        float4* op = reinterpret_cast<float4*>(O + ((size_t)b * SEQ + q_idx) * DIM + d0);
        op[0] = make_float4(oa.x * inv, oa.y * inv, oa.z * inv, oa.w * inv);
        op[1] = make_float4(ob.x * inv, ob.y * inv, ob.z * inv, ob.w * inv);
    }
}

extern "C" void kernel_launch(void* const* d_in, const int* in_sizes, int n_in,
                              void* d_out, int out_size) {
    const float* Q    = (const float*)d_in[0];
    const float* K    = (const float*)d_in[1];
    const float* V    = (const float*)d_in[2];
    const int*   mask = (const int*)d_in[3];
    float*       O    = (float*)d_out;

    reset_counter<<<1, 1>>>();
    sdpa_kernel<<<GRID, 256>>>(Q, K, V, mask, O);
}

// round 4
// speedup vs baseline: 8.7445x; 8.7445x over previous
#include <cuda_runtime.h>
#include <cstdint>

#define BATCH 4
#define SEQ   4096
#define DIM   64
#define BM    64          // q rows per CTA (4 warps x m16)
#define BN    64          // keys per tile
#define DIMP  68          // padded smem row stride (floats) -> conflict-free
#define NEGV  10000.0f

__device__ __forceinline__ uint32_t f2tf32(float f) {
    uint32_t u;
    asm("cvt.rna.tf32.f32 %0, %1;" : "=r"(u) : "f"(f));
    return u;
}

__device__ __forceinline__ void mma_tf32(float* d, const uint32_t* a, uint32_t b0, uint32_t b1) {
    asm("mma.sync.aligned.m16n8k8.row.col.f32.tf32.tf32.f32 "
        "{%0,%1,%2,%3},{%4,%5,%6,%7},{%8,%9},{%0,%1,%2,%3};"
        : "+f"(d[0]), "+f"(d[1]), "+f"(d[2]), "+f"(d[3])
        : "r"(a[0]), "r"(a[1]), "r"(a[2]), "r"(a[3]), "r"(b0), "r"(b1));
}

__global__ __launch_bounds__(128)
void sdpa_kernel(const float* __restrict__ Q, const float* __restrict__ K,
                 const float* __restrict__ V, const int* __restrict__ mask,
                 float* __restrict__ O) {
    __shared__ uint32_t Ks[BN][DIMP];   // tf32 bits
    __shared__ uint32_t Vs[BN][DIMP];
    __shared__ float    pen[BN];

    const int tid  = threadIdx.x;
    const int lane = tid & 31;
    const int warp = tid >> 5;
    const int g    = lane >> 2;      // fragment group row
    const int tig  = lane & 3;       // thread in group

    const int qb = (SEQ / BM - 1) - (blockIdx.x >> 2);   // longest first
    const int b  = blockIdx.x & 3;
    const int qm = qb * BM;
    const int* mb = mask + b * SEQ;

    // Any mask==1 in shared causal prefix [0..qm]? If yes, beyond-diagonal
    // scores sit >=10000 below the row max -> expf underflows to exact 0,
    // so tiles past the diagonal are skippable bit-exactly.
    int local = 0;
    for (int j = tid; j <= qm; j += 128) local |= mb[j];
    const int any_one = __syncthreads_or(local);
    const int n_tiles = any_one ? (qb + 1) : (SEQ / BN);

    const int r0 = qm + warp * 16 + g;       // this thread's two rows
    const int r1 = r0 + 8;

    // Q fragments: 8 k-chunks x {a0..a3}
    uint32_t qf[8][4];
    {
        const float* q0 = Q + ((size_t)b * SEQ + r0) * DIM;
        const float* q1 = Q + ((size_t)b * SEQ + r1) * DIM;
        #pragma unroll
        for (int kc = 0; kc < 8; kc++) {
            qf[kc][0] = f2tf32(q0[kc * 8 + tig]);
            qf[kc][1] = f2tf32(q1[kc * 8 + tig]);
            qf[kc][2] = f2tf32(q0[kc * 8 + tig + 4]);
            qf[kc][3] = f2tf32(q1[kc * 8 + tig + 4]);
        }
    }

    float o[8][4];
    #pragma unroll
    for (int i = 0; i < 8; i++)
        o[i][0] = o[i][1] = o[i][2] = o[i][3] = 0.0f;
    float m0 = -1e30f, m1 = -1e30f, l0 = 0.0f, l1 = 0.0f;

    for (int t = 0; t < n_tiles; t++) {
        const int kv0 = t * BN;
        __syncthreads();   // previous tile's smem reads done

        {   // stage K/V tile -> smem as tf32 (coalesced float4, cvt on the fly)
            const float4* kp = reinterpret_cast<const float4*>(K + ((size_t)b * SEQ + kv0) * DIM);
            const float4* vp = reinterpret_cast<const float4*>(V + ((size_t)b * SEQ + kv0) * DIM);
            #pragma unroll
            for (int i = 0; i < 8; i++) {
                const int v = tid + i * 128;          // float4 index, 0..1023
                const int row = v >> 4, c4 = (v & 15) * 4;
                float4 kk = kp[v], vv = vp[v];
                uint4 ku = make_uint4(f2tf32(kk.x), f2tf32(kk.y), f2tf32(kk.z), f2tf32(kk.w));
                uint4 vu = make_uint4(f2tf32(vv.x), f2tf32(vv.y), f2tf32(vv.z), f2tf32(vv.w));
                *reinterpret_cast<uint4*>(&Ks[row][c4]) = ku;
                *reinterpret_cast<uint4*>(&Vs[row][c4]) = vu;
            }
            if (tid < BN) pen[tid] = mb[kv0 + tid] ? 0.0f : -NEGV;
        }
        __syncthreads();

        // ---- S = Q K^T for this warp's 16 rows x 64 keys ----
        float s[8][4];
        #pragma unroll
        for (int nc = 0; nc < 8; nc++) {
            s[nc][0] = s[nc][1] = s[nc][2] = s[nc][3] = 0.0f;
            #pragma unroll
            for (int kc = 0; kc < 8; kc++) {
                uint32_t b0 = Ks[nc * 8 + g][kc * 8 + tig];
                uint32_t b1 = Ks[nc * 8 + g][kc * 8 + tig + 4];
                mma_tf32(s[nc], qf[kc], b0, b1);
            }
        }

        // ---- scale + penalties + row max ----
        float tmax0 = -1e30f, tmax1 = -1e30f;
        #pragma unroll
        for (int nc = 0; nc < 8; nc++) {
            const int c0 = kv0 + nc * 8 + 2 * tig;
            float2 pn = *reinterpret_cast<const float2*>(&pen[nc * 8 + 2 * tig]);
            s[nc][0] = s[nc][0] * 0.125f + pn.x + (c0     > r0 ? -NEGV : 0.0f);
            s[nc][1] = s[nc][1] * 0.125f + pn.y + (c0 + 1 > r0 ? -NEGV : 0.0f);
            s[nc][2] = s[nc][2] * 0.125f + pn.x + (c0     > r1 ? -NEGV : 0.0f);
            s[nc][3] = s[nc][3] * 0.125f + pn.y + (c0 + 1 > r1 ? -NEGV : 0.0f);
            tmax0 = fmaxf(tmax0, fmaxf(s[nc][0], s[nc][1]));
            tmax1 = fmaxf(tmax1, fmaxf(s[nc][2], s[nc][3]));
        }
        tmax0 = fmaxf(tmax0, __shfl_xor_sync(0xffffffffu, tmax0, 1));
        tmax0 = fmaxf(tmax0, __shfl_xor_sync(0xffffffffu, tmax0, 2));
        tmax1 = fmaxf(tmax1, __shfl_xor_sync(0xffffffffu, tmax1, 1));
        tmax1 = fmaxf(tmax1, __shfl_xor_sync(0xffffffffu, tmax1, 2));

        const float mn0 = fmaxf(m0, tmax0);
        const float mn1 = fmaxf(m1, tmax1);
        const float al0 = __expf(m0 - mn0);
        const float al1 = __expf(m1 - mn1);
        m0 = mn0; m1 = mn1;
        l0 *= al0; l1 *= al1;
        #pragma unroll
        for (int i = 0; i < 8; i++) {
            o[i][0] *= al0; o[i][1] *= al0;
            o[i][2] *= al1; o[i][3] *= al1;
        }

        // ---- P = exp(S - m), accumulate l (per-thread partial; quad-reduced at end) ----
        #pragma unroll
        for (int nc = 0; nc < 8; nc++) {
            s[nc][0] = __expf(s[nc][0] - m0);
            s[nc][1] = __expf(s[nc][1] - m0);
            s[nc][2] = __expf(s[nc][2] - m1);
            s[nc][3] = __expf(s[nc][3] - m1);
            l0 += s[nc][0] + s[nc][1];
            l1 += s[nc][2] + s[nc][3];
        }

        // ---- O += P V : per k-chunk, exchange C-layout -> A-layout, then mma ----
        const int base = lane & ~3;
        const int src1 = base + (tig >> 1);
        const int src2 = src1 + 2;
        const bool oddc = (tig & 1);
        #pragma unroll
        for (int kc = 0; kc < 8; kc++) {
            float e00 = __shfl_sync(0xffffffffu, s[kc][0], src1);
            float e01 = __shfl_sync(0xffffffffu, s[kc][1], src1);
            float e10 = __shfl_sync(0xffffffffu, s[kc][2], src1);
            float e11 = __shfl_sync(0xffffffffu, s[kc][3], src1);
            float f00 = __shfl_sync(0xffffffffu, s[kc][0], src2);
            float f01 = __shfl_sync(0xffffffffu, s[kc][1], src2);
            float f10 = __shfl_sync(0xffffffffu, s[kc][2], src2);
            float f11 = __shfl_sync(0xffffffffu, s[kc][3], src2);
            uint32_t pf[4];
            pf[0] = f2tf32(oddc ? e01 : e00);   // (row g,   col kc*8+tig)
            pf[1] = f2tf32(oddc ? e11 : e10);   // (row g+8, col kc*8+tig)
            pf[2] = f2tf32(oddc ? f01 : f00);   // (row g,   col kc*8+tig+4)
            pf[3] = f2tf32(oddc ? f11 : f10);   // (row g+8, col kc*8+tig+4)
            #pragma unroll
            for (int oc = 0; oc < 8; oc++) {
                uint32_t b0 = Vs[kc * 8 + tig][oc * 8 + g];
                uint32_t b1 = Vs[kc * 8 + tig + 4][oc * 8 + g];
                mma_tf32(o[oc], pf, b0, b1);
            }
        }
    }

    // ---- BUGFIX (R3): l held only this thread's 16 of 64 columns; reduce the
    // fragment quad so every thread normalizes by the full row sum. Exact:
    // m/alpha updates were already row-uniform across the quad. ----
    l0 += __shfl_xor_sync(0xffffffffu, l0, 1);
    l0 += __shfl_xor_sync(0xffffffffu, l0, 2);
    l1 += __shfl_xor_sync(0xffffffffu, l1, 1);
    l1 += __shfl_xor_sync(0xffffffffu, l1, 2);

    // ---- normalize + store (float2 per row per chunk) ----
    const float inv0 = 1.0f / l0;
    const float inv1 = 1.0f / l1;
    float* o0 = O + ((size_t)b * SEQ + r0) * DIM;
    float* o1 = O + ((size_t)b * SEQ + r1) * DIM;
    #pragma unroll
    for (int oc = 0; oc < 8; oc++) {
        const int c = oc * 8 + 2 * tig;
        *reinterpret_cast<float2*>(o0 + c) = make_float2(o[oc][0] * inv0, o[oc][1] * inv0);
        *reinterpret_cast<float2*>(o1 + c) = make_float2(o[oc][2] * inv1, o[oc][3] * inv1);
    }
}

extern "C" void kernel_launch(void* const* d_in, const int* in_sizes, int n_in,
                              void* d_out, int out_size) {
    const float* Q    = (const float*)d_in[0];
    const float* K    = (const float*)d_in[1];
    const float* V    = (const float*)d_in[2];
    const int*   mask = (const int*)d_in[3];
    float*       O    = (float*)d_out;

    dim3 grid((SEQ / BM) * BATCH);   // 256 CTAs
    sdpa_kernel<<<grid, 128>>>(Q, K, V, mask, O);
}

// round 5
// speedup vs baseline: 14.9253x; 1.7068x over previous
#include <cuda_runtime.h>
#include <cstdint>

#define BATCH  4
#define SEQ    4096
#define DIM    64
#define BM     64          // q rows per block
#define BN     64          // keys per tile
#define DIMP   68          // padded smem row stride (floats) -> conflict-free
#define NEGV   10000.0f
#define NSPLIT 4
#define NQB    (SEQ / BM)                 // 64
#define NP     (NQB * BATCH * NSPLIT)     // 1024 partials
#define STAGE_FLOATS 8704                 // K(4352) + V(4352) per stage
#define SMEM_BYTES   ((2 * STAGE_FLOATS + 2 * BN) * 4)   // 70144

__device__ float g_m[NP * BM];
__device__ float g_l[NP * BM];
__device__ float g_o[(size_t)NP * BM * DIM];

__device__ __forceinline__ uint32_t f2tf32(float f) {
    uint32_t u;
    asm("cvt.rna.tf32.f32 %0, %1;" : "=r"(u) : "f"(f));
    return u;
}

__device__ __forceinline__ void mma_tf32(float* d, const uint32_t* a, uint32_t b0, uint32_t b1) {
    asm("mma.sync.aligned.m16n8k8.row.col.f32.tf32.tf32.f32 "
        "{%0,%1,%2,%3},{%4,%5,%6,%7},{%8,%9},{%0,%1,%2,%3};"
        : "+f"(d[0]), "+f"(d[1]), "+f"(d[2]), "+f"(d[3])
        : "r"(a[0]), "r"(a[1]), "r"(a[2]), "r"(a[3]), "r"(b0), "r"(b1));
}

__global__ __launch_bounds__(128)
void sdpa_split_kernel(const float* __restrict__ Q, const float* __restrict__ K,
                       const float* __restrict__ V, const int* __restrict__ mask) {
    extern __shared__ float sm[];

    const int tid  = threadIdx.x;
    const int lane = tid & 31;
    const int warp = tid >> 5;
    const int g    = lane >> 2;
    const int tig  = lane & 3;

    const int bx = blockIdx.x;
    const int s  = bx & 3;
    const int b  = (bx >> 2) & 3;
    const int qb = (NQB - 1) - (bx >> 4);   // longest q-blocks first
    const int qm = qb * BM;
    const int p  = bx;                       // partial index
    const int* mb = mask + b * SEQ;

    // Any mask==1 in shared causal prefix [0..qm]? If yes, beyond-diagonal
    // scores are >=10000 below the row max -> expf underflows to exact 0,
    // so tiles past the diagonal are skippable bit-exactly.
    int local = 0;
    for (int j = tid; j <= qm; j += 128) local |= mb[j];
    const int any_one = __syncthreads_or(local);
    const int n_tiles = any_one ? (qb + 1) : (SEQ / BN);

    const int chunk = (n_tiles + NSPLIT - 1) / NSPLIT;
    const int t_beg = s * chunk;
    const int t_end = min(t_beg + chunk, n_tiles);

    const int lr0 = warp * 16 + g;    // local rows within the q-block
    const int lr1 = lr0 + 8;

    if (t_beg >= t_end) {             // empty split: sentinel partial
        if (tig == 0) {
            g_m[p * BM + lr0] = -1e30f; g_l[p * BM + lr0] = 0.0f;
            g_m[p * BM + lr1] = -1e30f; g_l[p * BM + lr1] = 0.0f;
        }
        return;
    }

    const int r0 = qm + lr0;          // global q rows
    const int r1 = qm + lr1;

    // Q fragments (rounded tf32)
    uint32_t qf[8][4];
    {
        const float* q0 = Q + ((size_t)b * SEQ + r0) * DIM;
        const float* q1 = Q + ((size_t)b * SEQ + r1) * DIM;
        #pragma unroll
        for (int kc = 0; kc < 8; kc++) {
            qf[kc][0] = f2tf32(q0[kc * 8 + tig]);
            qf[kc][1] = f2tf32(q1[kc * 8 + tig]);
            qf[kc][2] = f2tf32(q0[kc * 8 + tig + 4]);
            qf[kc][3] = f2tf32(q1[kc * 8 + tig + 4]);
        }
    }

    float o[8][4];
    #pragma unroll
    for (int i = 0; i < 8; i++)
        o[i][0] = o[i][1] = o[i][2] = o[i][3] = 0.0f;
    float m0 = -1e30f, m1 = -1e30f, l0 = 0.0f, l1 = 0.0f;

    // ---- async tile loader (raw fp32, cvt at fragment load) ----
    auto issue = [&](int t, int st) {
        const int kv0 = t * BN;
        const float4* kp = reinterpret_cast<const float4*>(K + ((size_t)b * SEQ + kv0) * DIM);
        const float4* vp = reinterpret_cast<const float4*>(V + ((size_t)b * SEQ + kv0) * DIM);
        float* Ksf = sm + st * STAGE_FLOATS;
        float* Vsf = Ksf + BN * DIMP;
        #pragma unroll
        for (int i = 0; i < 8; i++) {
            const int v = tid + i * 128;           // float4 idx 0..1023
            const int row = v >> 4, c4 = (v & 15) * 4;
            uint32_t ka = (uint32_t)__cvta_generic_to_shared(Ksf + row * DIMP + c4);
            uint32_t va = (uint32_t)__cvta_generic_to_shared(Vsf + row * DIMP + c4);
            asm volatile("cp.async.cg.shared.global [%0], [%1], 16;" :: "r"(ka), "l"(kp + v));
            asm volatile("cp.async.cg.shared.global [%0], [%1], 16;" :: "r"(va), "l"(vp + v));
        }
        float* penf = sm + 2 * STAGE_FLOATS + st * BN;
        if (tid < BN) penf[tid] = mb[kv0 + tid] ? 0.0f : -NEGV;
        asm volatile("cp.async.commit_group;");
    };

    issue(t_beg, 0);

    for (int t = t_beg; t < t_end; t++) {
        const int st  = (t - t_beg) & 1;
        const int kv0 = t * BN;

        if (t + 1 < t_end) {
            issue(t + 1, st ^ 1);
            asm volatile("cp.async.wait_group 1;");
        } else {
            asm volatile("cp.async.wait_group 0;");
        }
        __syncthreads();

        const float* Ksf  = sm + st * STAGE_FLOATS;
        const float* Vsf  = Ksf + BN * DIMP;
        const float* penf = sm + 2 * STAGE_FLOATS + st * BN;

        // ---- S = Q K^T (warp's 16 rows x 64 keys) ----
        float sc[8][4];
        #pragma unroll
        for (int nc = 0; nc < 8; nc++) {
            sc[nc][0] = sc[nc][1] = sc[nc][2] = sc[nc][3] = 0.0f;
            #pragma unroll
            for (int kc = 0; kc < 8; kc++) {
                uint32_t b0 = f2tf32(Ksf[(nc * 8 + g) * DIMP + kc * 8 + tig]);
                uint32_t b1 = f2tf32(Ksf[(nc * 8 + g) * DIMP + kc * 8 + tig + 4]);
                mma_tf32(sc[nc], qf[kc], b0, b1);
            }
        }

        // ---- scale + penalties + row max ----
        float tmax0 = -1e30f, tmax1 = -1e30f;
        #pragma unroll
        for (int nc = 0; nc < 8; nc++) {
            const int c0 = kv0 + nc * 8 + 2 * tig;
            float2 pn = *reinterpret_cast<const float2*>(penf + nc * 8 + 2 * tig);
            sc[nc][0] = sc[nc][0] * 0.125f + pn.x + (c0     > r0 ? -NEGV : 0.0f);
            sc[nc][1] = sc[nc][1] * 0.125f + pn.y + (c0 + 1 > r0 ? -NEGV : 0.0f);
            sc[nc][2] = sc[nc][2] * 0.125f + pn.x + (c0     > r1 ? -NEGV : 0.0f);
            sc[nc][3] = sc[nc][3] * 0.125f + pn.y + (c0 + 1 > r1 ? -NEGV : 0.0f);
            tmax0 = fmaxf(tmax0, fmaxf(sc[nc][0], sc[nc][1]));
            tmax1 = fmaxf(tmax1, fmaxf(sc[nc][2], sc[nc][3]));
        }
        tmax0 = fmaxf(tmax0, __shfl_xor_sync(0xffffffffu, tmax0, 1));
        tmax0 = fmaxf(tmax0, __shfl_xor_sync(0xffffffffu, tmax0, 2));
        tmax1 = fmaxf(tmax1, __shfl_xor_sync(0xffffffffu, tmax1, 1));
        tmax1 = fmaxf(tmax1, __shfl_xor_sync(0xffffffffu, tmax1, 2));

        const float mn0 = fmaxf(m0, tmax0);
        const float mn1 = fmaxf(m1, tmax1);
        const float al0 = __expf(m0 - mn0);
        const float al1 = __expf(m1 - mn1);
        m0 = mn0; m1 = mn1;
        l0 *= al0; l1 *= al1;
        #pragma unroll
        for (int i = 0; i < 8; i++) {
            o[i][0] *= al0; o[i][1] *= al0;
            o[i][2] *= al1; o[i][3] *= al1;
        }

        // ---- P = exp(S - m); l partial (quad-reduced at end) ----
        #pragma unroll
        for (int nc = 0; nc < 8; nc++) {
            sc[nc][0] = __expf(sc[nc][0] - m0);
            sc[nc][1] = __expf(sc[nc][1] - m0);
            sc[nc][2] = __expf(sc[nc][2] - m1);
            sc[nc][3] = __expf(sc[nc][3] - m1);
            l0 += sc[nc][0] + sc[nc][1];
            l1 += sc[nc][2] + sc[nc][3];
        }

        // ---- O += P V : C-layout -> A-layout exchange, then mma ----
        const int base = lane & ~3;
        const int src1 = base + (tig >> 1);
        const int src2 = src1 + 2;
        const bool oddc = (tig & 1);
        #pragma unroll
        for (int kc = 0; kc < 8; kc++) {
            float e00 = __shfl_sync(0xffffffffu, sc[kc][0], src1);
            float e01 = __shfl_sync(0xffffffffu, sc[kc][1], src1);
            float e10 = __shfl_sync(0xffffffffu, sc[kc][2], src1);
            float e11 = __shfl_sync(0xffffffffu, sc[kc][3], src1);
            float f00 = __shfl_sync(0xffffffffu, sc[kc][0], src2);
            float f01 = __shfl_sync(0xffffffffu, sc[kc][1], src2);
            float f10 = __shfl_sync(0xffffffffu, sc[kc][2], src2);
            float f11 = __shfl_sync(0xffffffffu, sc[kc][3], src2);
            uint32_t pf[4];
            pf[0] = f2tf32(oddc ? e01 : e00);
            pf[1] = f2tf32(oddc ? e11 : e10);
            pf[2] = f2tf32(oddc ? f01 : f00);
            pf[3] = f2tf32(oddc ? f11 : f10);
            #pragma unroll
            for (int oc = 0; oc < 8; oc++) {
                uint32_t b0 = f2tf32(Vsf[(kc * 8 + tig) * DIMP + oc * 8 + g]);
                uint32_t b1 = f2tf32(Vsf[(kc * 8 + tig + 4) * DIMP + oc * 8 + g]);
                mma_tf32(o[oc], pf, b0, b1);
            }
        }
        __syncthreads();
    }

    // quad-reduce l (full row sum)
    l0 += __shfl_xor_sync(0xffffffffu, l0, 1);
    l0 += __shfl_xor_sync(0xffffffffu, l0, 2);
    l1 += __shfl_xor_sync(0xffffffffu, l1, 1);
    l1 += __shfl_xor_sync(0xffffffffu, l1, 2);

    // store unnormalized partial + (m, l)
    float* po0 = g_o + ((size_t)p * BM + lr0) * DIM;
    float* po1 = g_o + ((size_t)p * BM + lr1) * DIM;
    #pragma unroll
    for (int oc = 0; oc < 8; oc++) {
        const int c = oc * 8 + 2 * tig;
        *reinterpret_cast<float2*>(po0 + c) = make_float2(o[oc][0], o[oc][1]);
        *reinterpret_cast<float2*>(po1 + c) = make_float2(o[oc][2], o[oc][3]);
    }
    if (tig == 0) {
        g_m[p * BM + lr0] = m0; g_l[p * BM + lr0] = l0;
        g_m[p * BM + lr1] = m1; g_l[p * BM + lr1] = l1;
    }
}

__global__ __launch_bounds__(256)
void combine_kernel(float* __restrict__ O) {
    const int blk = blockIdx.x;              // 0..255
    const int b   = blk >> 6;
    const int qb  = blk & 63;
    const int row = threadIdx.x >> 2;        // 0..63
    const int dq  = (threadIdx.x & 3) << 4;  // 16 dims per thread

    const int qidx  = (NQB - 1) - qb;        // matches main kernel's bx>>4
    const int pbase = ((qidx << 2) | b) << 2;

    float m[NSPLIT], l[NSPLIT], w[NSPLIT];
    float mmax = -1e30f;
    #pragma unroll
    for (int s = 0; s < NSPLIT; s++) {
        m[s] = g_m[(pbase + s) * BM + row];
        l[s] = g_l[(pbase + s) * BM + row];
        if (l[s] > 0.0f) mmax = fmaxf(mmax, m[s]);
    }
    float L = 0.0f;
    #pragma unroll
    for (int s = 0; s < NSPLIT; s++) {
        w[s] = (l[s] > 0.0f) ? __expf(m[s] - mmax) : 0.0f;
        L += w[s] * l[s];
    }
    const float inv = 1.0f / L;

    float4 acc[4];
    #pragma unroll
    for (int i = 0; i < 4; i++) acc[i] = make_float4(0.f, 0.f, 0.f, 0.f);
    #pragma unroll
    for (int s = 0; s < NSPLIT; s++) {
        if (w[s] != 0.0f) {
            const float4* op = reinterpret_cast<const float4*>(
                g_o + ((size_t)(pbase + s) * BM + row) * DIM + dq);
            #pragma unroll
            for (int i = 0; i < 4; i++) {
                float4 v = op[i];
                acc[i].x += w[s] * v.x; acc[i].y += w[s] * v.y;
                acc[i].z += w[s] * v.z; acc[i].w += w[s] * v.w;
            }
        }
    }
    float4* out = reinterpret_cast<float4*>(
        O + ((size_t)b * SEQ + qb * BM + row) * DIM + dq);
    #pragma unroll
    for (int i = 0; i < 4; i++)
        out[i] = make_float4(acc[i].x * inv, acc[i].y * inv, acc[i].z * inv, acc[i].w * inv);
}

extern "C" void kernel_launch(void* const* d_in, const int* in_sizes, int n_in,
                              void* d_out, int out_size) {
    const float* Q    = (const float*)d_in[0];
    const float* K    = (const float*)d_in[1];
    const float* V    = (const float*)d_in[2];
    const int*   mask = (const int*)d_in[3];
    float*       O    = (float*)d_out;

    cudaFuncSetAttribute(sdpa_split_kernel,
                         cudaFuncAttributeMaxDynamicSharedMemorySize, SMEM_BYTES);
    sdpa_split_kernel<<<NP, 128, SMEM_BYTES>>>(Q, K, V, mask);
    combine_kernel<<<BATCH * NQB, 256>>>(O);
}